// round 3
// baseline (speedup 1.0000x reference)
#include <cuda_runtime.h>

typedef unsigned long long u64;

#define NBMAX 28          // batches per CTA
#define NPMAX 14          // batch pairs per CTA
#define HDIM  64
#define GDIM  256         // 4*HDIM gate rows
#define IDIM  8
#define NTHR  512

// ---- packed f32x2 helpers (Blackwell sm_100a) ----
__device__ __forceinline__ u64 ffma2(u64 a, u64 b, u64 c) {
    u64 r;
    asm("fma.rn.f32x2 %0, %1, %2, %3;" : "=l"(r) : "l"(a), "l"(b), "l"(c));
    return r;
}
__device__ __forceinline__ u64 addf2(u64 a, u64 b) {
    u64 r;
    asm("add.rn.f32x2 %0, %1, %2;" : "=l"(r) : "l"(a), "l"(b));
    return r;
}
__device__ __forceinline__ u64 pack2(float x, float y) {
    u64 r;
    asm("mov.b64 %0, {%1, %2};" : "=l"(r) : "f"(x), "f"(y));
    return r;
}

// ---- activations: __expf is MUFU-based, ~1e-7 rel err ----
__device__ __forceinline__ float sigm_f(float x) {
    return 1.0f / (1.0f + __expf(-x));
}
__device__ __forceinline__ float tanh_f(float x) {
    return fmaf(2.0f, 1.0f / (1.0f + __expf(-2.0f * x)), -1.0f);
}

__global__ void __launch_bounds__(NTHR, 1) lstm_persistent_kernel(
    const float* __restrict__ x,      // [B, T, I]
    const float* __restrict__ Wih,    // [4H, I]
    const float* __restrict__ Whh,    // [4H, H]
    const float* __restrict__ bih,    // [4H]
    const float* __restrict__ bhh,    // [4H]
    const float* __restrict__ Wfc,    // [1, H]
    const float* __restrict__ bfc,    // [1]
    float* __restrict__ out,          // [B, 1]
    int B, int T)
{
    // SMEM: packed-by-batch-pair buffers. u64 = (float b_even, float b_odd)
    __shared__ __align__(16) u64 gates[NPMAX * GDIM];   // 28 KB
    __shared__ __align__(16) u64 hbuf[NPMAX * HDIM];    // 7 KB
    __shared__ __align__(16) u64 xs[2][NPMAX * IDIM];   // 1.75 KB (double buffer)

    const int tid = threadIdx.x;
    const int s   = tid & 1;          // row half (0: k<32 / i<4, 1: upper halves)
    const int j   = tid >> 1;         // gate row 0..255
    const int b0  = blockIdx.x * NBMAX;
    const int nb  = min(NBMAX, B - b0);
    const int np  = (nb + 1) >> 1;          // batch pairs
    const int ntask = np * 2 * HDIM;        // pointwise tasks
    const int nx  = nb * IDIM;              // x scalars per step

    // ---- preload half a gate row of weights into registers, packed (w,w) ----
    u64 whh2[32];
#pragma unroll
    for (int k = 0; k < 32; ++k) {
        float w = Whh[j * HDIM + s * 32 + k];
        whh2[k] = pack2(w, w);
    }
    u64 wih2[4];
#pragma unroll
    for (int i = 0; i < 4; ++i) {
        float w = Wih[j * IDIM + s * 4 + i];
        wih2[i] = pack2(w, w);
    }
    const float bsum = bih[j] + bhh[j];
    const u64 bias2 = s ? 0ull : pack2(bsum, bsum);

    // ---- zero h, x buffers ----
    for (int idx = tid; idx < NPMAX * HDIM; idx += NTHR) hbuf[idx] = 0ull;
    for (int idx = tid; idx < NPMAX * IDIM; idx += NTHR) { xs[0][idx] = 0ull; xs[1][idx] = 0ull; }

    // ---- pointwise task precompute (time-invariant): idx = tid + NTHR*r ----
    float creg[4];
    int   goff[4], hoff[4];
    bool  pok[4];
#pragma unroll
    for (int r = 0; r < 4; ++r) {
        const int idx = tid + NTHR * r;
        pok[r] = (idx < ntask);
        const int p = idx >> 7;
        const int e = (idx >> 6) & 1;
        const int u = idx & 63;
        goff[r] = (p * GDIM + u) * 2 + e;   // float index; +128/+256/+384 for f,g,o
        hoff[r] = (p * HDIM + u) * 2 + e;
        creg[r] = 0.0f;
    }

    // ---- load x(t=0) into xs[0] ----
    int xp = 0, xe = 0, xi = 0;
    if (tid < nx) {
        xp = tid >> 4;            // pair
        xe = (tid >> 3) & 1;      // half within pair
        xi = tid & 7;             // input feature
        float v = x[((size_t)(b0 + 2 * xp + xe) * T) * IDIM + xi];
        ((float*)&xs[0][xp * IDIM + xi])[xe] = v;
    }
    __syncthreads();

    const float* gatesf = (const float*)gates;
    float* hbuff = (float*)hbuf;

    for (int t = 0; t < T; ++t) {
        // prefetch x(t+1) into a register (latency hidden by matvec)
        float xn = 0.0f;
        const bool do_x = (t + 1 < T) && (tid < nx);
        if (do_x)
            xn = x[((size_t)(b0 + 2 * xp + xe) * T + (t + 1)) * IDIM + xi];

        const u64* xcur = xs[t & 1];

        // ---- matvec: half-row partial dot, two batch pairs at a time ----
        for (int p = 0; p < np; p += 2) {
            const bool two = (p + 1 < np);
            u64 a0 = bias2, a1 = bias2;
            const u64* h0 = hbuf + p * HDIM + s * 32;
            const u64* h1 = h0 + HDIM;
            const u64* x0 = xcur + p * IDIM + s * 4;
            const u64* x1 = x0 + IDIM;
#pragma unroll
            for (int i = 0; i < 4; i += 2) {
                ulonglong2 xv0 = *(const ulonglong2*)(x0 + i);
                a0 = ffma2(xv0.x, wih2[i], a0);
                a0 = ffma2(xv0.y, wih2[i + 1], a0);
                if (two) {
                    ulonglong2 xv1 = *(const ulonglong2*)(x1 + i);
                    a1 = ffma2(xv1.x, wih2[i], a1);
                    a1 = ffma2(xv1.y, wih2[i + 1], a1);
                }
            }
#pragma unroll
            for (int k = 0; k < 32; k += 2) {
                ulonglong2 hv0 = *(const ulonglong2*)(h0 + k);
                a0 = ffma2(hv0.x, whh2[k], a0);
                a0 = ffma2(hv0.y, whh2[k + 1], a0);
                if (two) {
                    ulonglong2 hv1 = *(const ulonglong2*)(h1 + k);
                    a1 = ffma2(hv1.x, whh2[k], a1);
                    a1 = ffma2(hv1.y, whh2[k + 1], a1);
                }
            }
            // combine lane-pair halves: lanes (2l, 2l+1) hold the two halves of row j
            a0 = addf2(a0, __shfl_xor_sync(0xFFFFFFFFu, a0, 1));
            if (two) a1 = addf2(a1, __shfl_xor_sync(0xFFFFFFFFu, a1, 1));
            if (!s) {
                gates[p * GDIM + j] = a0;
                if (two) gates[(p + 1) * GDIM + j] = a1;
            }
        }

        // stash prefetched x into the other buffer (visible after barrier)
        if (do_x)
            ((float*)&xs[(t + 1) & 1][xp * IDIM + xi])[xe] = xn;

        __syncthreads();

        // ---- pointwise: i,f,g,o -> c,h ----
#pragma unroll
        for (int r = 0; r < 4; ++r) {
            if (pok[r]) {
                const int g0 = goff[r];
                float gi = gatesf[g0];
                float gf = gatesf[g0 + 128];
                float gg = gatesf[g0 + 256];
                float go = gatesf[g0 + 384];
                float iv = sigm_f(gi);
                float fv = sigm_f(gf);
                float gv = tanh_f(gg);
                float ov = sigm_f(go);
                float c  = fmaf(fv, creg[r], iv * gv);
                creg[r] = c;
                hbuff[hoff[r]] = ov * tanh_f(c);
            }
        }
        __syncthreads();
    }

    // ---- final FC: out[b] = h_T . Wfc + bfc ----
    if (tid < nb) {
        const int p = tid >> 1, e = tid & 1;
        float sum = bfc[0];
#pragma unroll
        for (int u = 0; u < HDIM; ++u)
            sum = fmaf(hbuff[(p * HDIM + u) * 2 + e], Wfc[u], sum);
        out[b0 + tid] = sum;
    }
}

extern "C" void kernel_launch(void* const* d_in, const int* in_sizes, int n_in,
                              void* d_out, int out_size) {
    const float* x    = (const float*)d_in[0];
    const float* Wih  = (const float*)d_in[1];
    const float* Whh  = (const float*)d_in[2];
    const float* bih  = (const float*)d_in[3];
    const float* bhh  = (const float*)d_in[4];
    const float* Wfc  = (const float*)d_in[5];
    const float* bfc  = (const float*)d_in[6];
    float* out = (float*)d_out;

    const int B = out_size;                   // O = 1
    const int T = in_sizes[0] / (B * IDIM);

    const int grid = (B + NBMAX - 1) / NBMAX;
    lstm_persistent_kernel<<<grid, NTHR>>>(x, Wih, Whh, bih, bhh, Wfc, bfc, out, B, T);
}

// round 4
// speedup vs baseline: 1.3583x; 1.3583x over previous
#include <cuda_runtime.h>

typedef unsigned long long u64;

#define NBMAX 28          // batches per CTA
#define NPMAX 14          // batch pairs per CTA
#define HDIM  64
#define GDIM  256         // 4*HDIM gate rows
#define IDIM  8
#define NTHR  256

// ---- packed f32x2 helpers (Blackwell sm_100a) ----
__device__ __forceinline__ u64 ffma2(u64 a, u64 b, u64 c) {
    u64 r;
    asm("fma.rn.f32x2 %0, %1, %2, %3;" : "=l"(r) : "l"(a), "l"(b), "l"(c));
    return r;
}
__device__ __forceinline__ u64 pack2(float x, float y) {
    u64 r;
    asm("mov.b64 %0, {%1, %2};" : "=l"(r) : "f"(x), "f"(y));
    return r;
}

// ---- activations: __expf is MUFU-based, ~1e-7 rel err ----
__device__ __forceinline__ float sigm_f(float x) {
    return 1.0f / (1.0f + __expf(-x));
}
__device__ __forceinline__ float tanh_f(float x) {
    return fmaf(2.0f, 1.0f / (1.0f + __expf(-2.0f * x)), -1.0f);
}

__global__ void __launch_bounds__(NTHR, 1) lstm_persistent_kernel(
    const float* __restrict__ x,      // [B, T, I]
    const float* __restrict__ Wih,    // [4H, I]
    const float* __restrict__ Whh,    // [4H, H]
    const float* __restrict__ bih,    // [4H]
    const float* __restrict__ bhh,    // [4H]
    const float* __restrict__ Wfc,    // [1, H]
    const float* __restrict__ bfc,    // [1]
    float* __restrict__ out,          // [B, 1]
    int B, int T)
{
    // SMEM: packed-by-batch-pair buffers. u64 = (float b_even, float b_odd)
    __shared__ __align__(16) u64 gates[NPMAX * GDIM];   // 28 KB
    __shared__ __align__(16) u64 hbuf[NPMAX * HDIM];    // 7 KB
    __shared__ __align__(16) u64 xs[2][NPMAX * IDIM];   // 1.75 KB (double buffer)

    const int tid = threadIdx.x;
    const int b0  = blockIdx.x * NBMAX;
    const int nb  = min(NBMAX, B - b0);
    const int np  = (nb + 1) >> 1;          // batch pairs
    const int ntask = np * 2 * HDIM;        // pointwise tasks
    const int nx  = nb * IDIM;              // x scalars per step

    // ---- preload gate row weights into registers, packed (w,w) ----
    u64 whh2[HDIM];
#pragma unroll
    for (int k = 0; k < HDIM; ++k) {
        float w = Whh[tid * HDIM + k];
        whh2[k] = pack2(w, w);
    }
    u64 wih2[IDIM];
#pragma unroll
    for (int i = 0; i < IDIM; ++i) {
        float w = Wih[tid * IDIM + i];
        wih2[i] = pack2(w, w);
    }
    const float bsum = bih[tid] + bhh[tid];
    const u64 bias2 = pack2(bsum, bsum);

    // ---- zero h, x buffers ----
    for (int idx = tid; idx < NPMAX * HDIM; idx += NTHR) hbuf[idx] = 0ull;
    for (int idx = tid; idx < NPMAX * IDIM; idx += NTHR) { xs[0][idx] = 0ull; xs[1][idx] = 0ull; }

    // ---- pointwise task precompute (time-invariant): idx = tid + NTHR*r ----
    float creg[7];
    int   goff[7], hoff[7];
    bool  pok[7];
#pragma unroll
    for (int r = 0; r < 7; ++r) {
        const int idx = tid + NTHR * r;
        pok[r] = (idx < ntask);
        const int p = idx >> 7;
        const int e = (idx >> 6) & 1;
        const int u = idx & 63;
        goff[r] = (p * GDIM + u) * 2 + e;   // float index; +128/+256/+384 for f,g,o
        hoff[r] = (p * HDIM + u) * 2 + e;
        creg[r] = 0.0f;
    }

    // ---- load x(t=0) into xs[0] ----
    int xp = 0, xe = 0, xi = 0;
    if (tid < nx) {
        xp = tid >> 4;            // pair
        xe = (tid >> 3) & 1;      // half within pair
        xi = tid & 7;             // input feature
        float v = x[((size_t)(b0 + 2 * xp + xe) * T) * IDIM + xi];
        ((float*)&xs[0][xp * IDIM + xi])[xe] = v;
    }
    __syncthreads();

    const float* gatesf = (const float*)gates;
    float* hbuff = (float*)hbuf;

    for (int t = 0; t < T; ++t) {
        // prefetch x(t+1) into a register (latency hidden by matvec)
        float xn = 0.0f;
        const bool do_x = (t + 1 < T) && (tid < nx);
        if (do_x)
            xn = x[((size_t)(b0 + 2 * xp + xe) * T + (t + 1)) * IDIM + xi];

        const u64* xcur = xs[t & 1];

        // ---- matvec: gate[j] = bias + Wih.x + Whh.h, FOUR batch pairs at a time ----
        for (int p = 0; p < np; p += 4) {
            const bool v1 = (p + 1 < np);
            const bool v2 = (p + 2 < np);
            const bool v3 = (p + 3 < np);
            u64 a0 = bias2, a1 = bias2, a2 = bias2, a3 = bias2;
            const u64* h0 = hbuf + p * HDIM;
            const u64* x0 = xcur + p * IDIM;
#pragma unroll
            for (int i = 0; i < IDIM; i += 2) {
                ulonglong2 xv0 = *(const ulonglong2*)(x0 + i);
                a0 = ffma2(xv0.x, wih2[i], a0);
                a0 = ffma2(xv0.y, wih2[i + 1], a0);
                if (v1) {
                    ulonglong2 xv1 = *(const ulonglong2*)(x0 + IDIM + i);
                    a1 = ffma2(xv1.x, wih2[i], a1);
                    a1 = ffma2(xv1.y, wih2[i + 1], a1);
                }
                if (v2) {
                    ulonglong2 xv2 = *(const ulonglong2*)(x0 + 2 * IDIM + i);
                    a2 = ffma2(xv2.x, wih2[i], a2);
                    a2 = ffma2(xv2.y, wih2[i + 1], a2);
                }
                if (v3) {
                    ulonglong2 xv3 = *(const ulonglong2*)(x0 + 3 * IDIM + i);
                    a3 = ffma2(xv3.x, wih2[i], a3);
                    a3 = ffma2(xv3.y, wih2[i + 1], a3);
                }
            }
#pragma unroll
            for (int k = 0; k < HDIM; k += 2) {
                ulonglong2 hv0 = *(const ulonglong2*)(h0 + k);
                a0 = ffma2(hv0.x, whh2[k], a0);
                a0 = ffma2(hv0.y, whh2[k + 1], a0);
                if (v1) {
                    ulonglong2 hv1 = *(const ulonglong2*)(h0 + HDIM + k);
                    a1 = ffma2(hv1.x, whh2[k], a1);
                    a1 = ffma2(hv1.y, whh2[k + 1], a1);
                }
                if (v2) {
                    ulonglong2 hv2 = *(const ulonglong2*)(h0 + 2 * HDIM + k);
                    a2 = ffma2(hv2.x, whh2[k], a2);
                    a2 = ffma2(hv2.y, whh2[k + 1], a2);
                }
                if (v3) {
                    ulonglong2 hv3 = *(const ulonglong2*)(h0 + 3 * HDIM + k);
                    a3 = ffma2(hv3.x, whh2[k], a3);
                    a3 = ffma2(hv3.y, whh2[k + 1], a3);
                }
            }
            gates[p * GDIM + tid] = a0;
            if (v1) gates[(p + 1) * GDIM + tid] = a1;
            if (v2) gates[(p + 2) * GDIM + tid] = a2;
            if (v3) gates[(p + 3) * GDIM + tid] = a3;
        }

        // stash prefetched x into the other buffer (visible after barrier)
        if (do_x)
            ((float*)&xs[(t + 1) & 1][xp * IDIM + xi])[xe] = xn;

        __syncthreads();

        // ---- pointwise: i,f,g,o -> c,h ----
#pragma unroll
        for (int r = 0; r < 7; ++r) {
            if (pok[r]) {
                const int g0 = goff[r];
                float gi = gatesf[g0];
                float gf = gatesf[g0 + 128];
                float gg = gatesf[g0 + 256];
                float go = gatesf[g0 + 384];
                float iv = sigm_f(gi);
                float fv = sigm_f(gf);
                float gv = tanh_f(gg);
                float ov = sigm_f(go);
                float c  = fmaf(fv, creg[r], iv * gv);
                creg[r] = c;
                hbuff[hoff[r]] = ov * tanh_f(c);
            }
        }
        __syncthreads();
    }

    // ---- final FC: out[b] = h_T . Wfc + bfc ----
    if (tid < nb) {
        const int p = tid >> 1, e = tid & 1;
        float sum = bfc[0];
#pragma unroll
        for (int u = 0; u < HDIM; ++u)
            sum = fmaf(hbuff[(p * HDIM + u) * 2 + e], Wfc[u], sum);
        out[b0 + tid] = sum;
    }
}

extern "C" void kernel_launch(void* const* d_in, const int* in_sizes, int n_in,
                              void* d_out, int out_size) {
    const float* x    = (const float*)d_in[0];
    const float* Wih  = (const float*)d_in[1];
    const float* Whh  = (const float*)d_in[2];
    const float* bih  = (const float*)d_in[3];
    const float* bhh  = (const float*)d_in[4];
    const float* Wfc  = (const float*)d_in[5];
    const float* bfc  = (const float*)d_in[6];
    float* out = (float*)d_out;

    const int B = out_size;                   // O = 1
    const int T = in_sizes[0] / (B * IDIM);

    const int grid = (B + NBMAX - 1) / NBMAX;
    lstm_persistent_kernel<<<grid, NTHR>>>(x, Wih, Whh, bih, bhh, Wfc, bfc, out, B, T);
}

// round 5
// speedup vs baseline: 1.4822x; 1.0912x over previous
#include <cuda_runtime.h>

typedef unsigned long long u64;

#define HDIM  64
#define GDIM  256         // 4*HDIM gate rows
#define IDIM  8
#define NTHR  256
#define NP    14          // batch pairs per CTA (compile-time!)
#define NB    (2 * NP)    // 28 batches per CTA
#define NR    (NP / 2)    // pointwise tasks per thread = NP*128/256

// ---- packed f32x2 helpers (Blackwell sm_100a) ----
__device__ __forceinline__ u64 ffma2(u64 a, u64 b, u64 c) {
    u64 r;
    asm("fma.rn.f32x2 %0, %1, %2, %3;" : "=l"(r) : "l"(a), "l"(b), "l"(c));
    return r;
}
__device__ __forceinline__ u64 pack2(float x, float y) {
    u64 r;
    asm("mov.b64 %0, {%1, %2};" : "=l"(r) : "f"(x), "f"(y));
    return r;
}

// ---- activations: __expf is MUFU-based, ~1e-7 rel err ----
__device__ __forceinline__ float sigm_f(float x) {
    return 1.0f / (1.0f + __expf(-x));
}
__device__ __forceinline__ float tanh_f(float x) {
    return fmaf(2.0f, 1.0f / (1.0f + __expf(-2.0f * x)), -1.0f);
}

__global__ void __launch_bounds__(NTHR, 1) lstm_persistent_kernel(
    const float* __restrict__ x,      // [B, T, I]
    const float* __restrict__ Wih,    // [4H, I]
    const float* __restrict__ Whh,    // [4H, H]
    const float* __restrict__ bih,    // [4H]
    const float* __restrict__ bhh,    // [4H]
    const float* __restrict__ Wfc,    // [1, H]
    const float* __restrict__ bfc,    // [1]
    float* __restrict__ out,          // [B, 1]
    int B, int T)
{
    // SMEM: packed-by-batch-pair buffers. u64 = (float b_even, float b_odd)
    __shared__ __align__(16) u64 gates[NP * GDIM];   // 28 KB
    __shared__ __align__(16) u64 hbuf[NP * HDIM];    // 7 KB
    __shared__ __align__(16) u64 xs[2][NP * IDIM];   // 1.75 KB (double buffer)

    const int tid = threadIdx.x;
    const int b0  = blockIdx.x * NB;
    const int nb  = min(NB, B - b0);        // only affects x-load / out guards
    const int nx  = nb * IDIM;              // x scalars per step

    // ---- preload gate row weights into registers, packed (w,w) ----
    u64 whh2[HDIM];
#pragma unroll
    for (int k = 0; k < HDIM; ++k) {
        float w = Whh[tid * HDIM + k];
        whh2[k] = pack2(w, w);
    }
    u64 wih2[IDIM];
#pragma unroll
    for (int i = 0; i < IDIM; ++i) {
        float w = Wih[tid * IDIM + i];
        wih2[i] = pack2(w, w);
    }
    const float bsum = bih[tid] + bhh[tid];
    const u64 bias2 = pack2(bsum, bsum);

    // ---- zero h, x buffers (phantom batches stay zero -> bounded garbage, no OOB) ----
    for (int idx = tid; idx < NP * HDIM; idx += NTHR) hbuf[idx] = 0ull;
    for (int idx = tid; idx < NP * IDIM; idx += NTHR) { xs[0][idx] = 0ull; xs[1][idx] = 0ull; }

    // ---- pointwise task precompute (time-invariant, exact: NR*NTHR == NP*128) ----
    float creg[NR];
    int   goff[NR], hoff[NR];
#pragma unroll
    for (int r = 0; r < NR; ++r) {
        const int idx = tid + NTHR * r;
        const int p = idx >> 7;
        const int e = (idx >> 6) & 1;
        const int u = idx & 63;
        goff[r] = (p * GDIM + u) * 2 + e;   // float index; +128/+256/+384 for f,g,o
        hoff[r] = (p * HDIM + u) * 2 + e;
        creg[r] = 0.0f;
    }

    // ---- load x(t=0) into xs[0] ----
    int xp = 0, xe = 0, xi = 0;
    if (tid < nx) {
        xp = tid >> 4;            // pair
        xe = (tid >> 3) & 1;      // half within pair
        xi = tid & 7;             // input feature
        float v = x[((size_t)(b0 + 2 * xp + xe) * T) * IDIM + xi];
        ((float*)&xs[0][xp * IDIM + xi])[xe] = v;
    }
    __syncthreads();

    const float* gatesf = (const float*)gates;
    float* hbuff = (float*)hbuf;

    for (int t = 0; t < T; ++t) {
        // prefetch x(t+1) into a register (latency hidden by matvec)
        float xn = 0.0f;
        const bool do_x = (t + 1 < T) && (tid < nx);
        if (do_x)
            xn = x[((size_t)(b0 + 2 * xp + xe) * T + (t + 1)) * IDIM + xi];

        const u64* xcur = xs[t & 1];

        // ---- matvec: FOUR batch pairs at a time, all bounds compile-time ----
#pragma unroll
        for (int p = 0; p < NP; p += 4) {
            constexpr int PMAX = NP;
            const bool v1 = (p + 1 < PMAX);   // folds at compile time
            const bool v2 = (p + 2 < PMAX);
            const bool v3 = (p + 3 < PMAX);
            u64 a0 = bias2, a1 = bias2, a2 = bias2, a3 = bias2;
            const u64* h0 = hbuf + p * HDIM;
            const u64* x0 = xcur + p * IDIM;
#pragma unroll
            for (int i = 0; i < IDIM; i += 2) {
                ulonglong2 xv0 = *(const ulonglong2*)(x0 + i);
                a0 = ffma2(xv0.x, wih2[i], a0);
                a0 = ffma2(xv0.y, wih2[i + 1], a0);
                if (v1) {
                    ulonglong2 xv1 = *(const ulonglong2*)(x0 + IDIM + i);
                    a1 = ffma2(xv1.x, wih2[i], a1);
                    a1 = ffma2(xv1.y, wih2[i + 1], a1);
                }
                if (v2) {
                    ulonglong2 xv2 = *(const ulonglong2*)(x0 + 2 * IDIM + i);
                    a2 = ffma2(xv2.x, wih2[i], a2);
                    a2 = ffma2(xv2.y, wih2[i + 1], a2);
                }
                if (v3) {
                    ulonglong2 xv3 = *(const ulonglong2*)(x0 + 3 * IDIM + i);
                    a3 = ffma2(xv3.x, wih2[i], a3);
                    a3 = ffma2(xv3.y, wih2[i + 1], a3);
                }
            }
#pragma unroll
            for (int k = 0; k < HDIM; k += 2) {
                ulonglong2 hv0 = *(const ulonglong2*)(h0 + k);
                a0 = ffma2(hv0.x, whh2[k], a0);
                a0 = ffma2(hv0.y, whh2[k + 1], a0);
                if (v1) {
                    ulonglong2 hv1 = *(const ulonglong2*)(h0 + HDIM + k);
                    a1 = ffma2(hv1.x, whh2[k], a1);
                    a1 = ffma2(hv1.y, whh2[k + 1], a1);
                }
                if (v2) {
                    ulonglong2 hv2 = *(const ulonglong2*)(h0 + 2 * HDIM + k);
                    a2 = ffma2(hv2.x, whh2[k], a2);
                    a2 = ffma2(hv2.y, whh2[k + 1], a2);
                }
                if (v3) {
                    ulonglong2 hv3 = *(const ulonglong2*)(h0 + 3 * HDIM + k);
                    a3 = ffma2(hv3.x, whh2[k], a3);
                    a3 = ffma2(hv3.y, whh2[k + 1], a3);
                }
            }
            gates[p * GDIM + tid] = a0;
            if (v1) gates[(p + 1) * GDIM + tid] = a1;
            if (v2) gates[(p + 2) * GDIM + tid] = a2;
            if (v3) gates[(p + 3) * GDIM + tid] = a3;
        }

        // stash prefetched x into the other buffer (visible after barrier)
        if (do_x)
            ((float*)&xs[(t + 1) & 1][xp * IDIM + xi])[xe] = xn;

        __syncthreads();

        // ---- pointwise: i,f,g,o -> c,h (no predicates; exact task tiling) ----
#pragma unroll
        for (int r = 0; r < NR; ++r) {
            const int g0 = goff[r];
            float gi = gatesf[g0];
            float gf = gatesf[g0 + 128];
            float gg = gatesf[g0 + 256];
            float go = gatesf[g0 + 384];
            float iv = sigm_f(gi);
            float fv = sigm_f(gf);
            float gv = tanh_f(gg);
            float ov = sigm_f(go);
            float c  = fmaf(fv, creg[r], iv * gv);
            creg[r] = c;
            hbuff[hoff[r]] = ov * tanh_f(c);
        }
        __syncthreads();
    }

    // ---- final FC: out[b] = h_T . Wfc + bfc ----
    if (tid < nb) {
        const int p = tid >> 1, e = tid & 1;
        float sum = bfc[0];
#pragma unroll
        for (int u = 0; u < HDIM; ++u)
            sum = fmaf(hbuff[(p * HDIM + u) * 2 + e], Wfc[u], sum);
        out[b0 + tid] = sum;
    }
}

extern "C" void kernel_launch(void* const* d_in, const int* in_sizes, int n_in,
                              void* d_out, int out_size) {
    const float* x    = (const float*)d_in[0];
    const float* Wih  = (const float*)d_in[1];
    const float* Whh  = (const float*)d_in[2];
    const float* bih  = (const float*)d_in[3];
    const float* bhh  = (const float*)d_in[4];
    const float* Wfc  = (const float*)d_in[5];
    const float* bfc  = (const float*)d_in[6];
    float* out = (float*)d_out;

    const int B = out_size;                   // O = 1
    const int T = in_sizes[0] / (B * IDIM);

    const int grid = (B + NB - 1) / NB;
    lstm_persistent_kernel<<<grid, NTHR>>>(x, Wih, Whh, bih, bhh, Wfc, bfc, out, B, T);
}

// round 6
// speedup vs baseline: 1.5903x; 1.0729x over previous
#include <cuda_runtime.h>

typedef unsigned long long u64;

#define HDIM  64
#define GDIM  256         // 4*HDIM gate rows
#define IDIM  8
#define NTHR  512
#define NP    14          // batch pairs per CTA
#define NB    (2 * NP)    // 28 batches per CTA
#define TP    7           // pairs per team (two teams of 256 threads)
#define NTASK (NP * 128)  // 1792 pointwise tasks
#define NR    4           // pointwise tasks per thread (ceil 1792/512)

// SMEM layout (dynamic): wsm[64][256] f32 | gates[NP*GDIM] u64 | hbuf[NP*HDIM] u64 | xs[2][NP*IDIM] u64
#define WSM_BYTES   (HDIM * GDIM * 4)            // 65536
#define GATES_BYTES (NP * GDIM * 8)              // 28672
#define HBUF_BYTES  (NP * HDIM * 8)              // 7168
#define XS_BYTES    (2 * NP * IDIM * 8)          // 1792
#define SMEM_BYTES  (WSM_BYTES + GATES_BYTES + HBUF_BYTES + XS_BYTES)

// ---- packed f32x2 helpers (Blackwell sm_100a) ----
__device__ __forceinline__ u64 ffma2(u64 a, u64 b, u64 c) {
    u64 r;
    asm("fma.rn.f32x2 %0, %1, %2, %3;" : "=l"(r) : "l"(a), "l"(b), "l"(c));
    return r;
}
__device__ __forceinline__ u64 pack2(float x, float y) {
    u64 r;
    asm("mov.b64 %0, {%1, %2};" : "=l"(r) : "f"(x), "f"(y));
    return r;
}

// ---- activations: __expf is MUFU-based, ~1e-7 rel err ----
__device__ __forceinline__ float sigm_f(float x) {
    return 1.0f / (1.0f + __expf(-x));
}
__device__ __forceinline__ float tanh_f(float x) {
    return fmaf(2.0f, 1.0f / (1.0f + __expf(-2.0f * x)), -1.0f);
}

__global__ void __launch_bounds__(NTHR, 1) lstm_persistent_kernel(
    const float* __restrict__ x,      // [B, T, I]
    const float* __restrict__ Wih,    // [4H, I]
    const float* __restrict__ Whh,    // [4H, H]
    const float* __restrict__ bih,    // [4H]
    const float* __restrict__ bhh,    // [4H]
    const float* __restrict__ Wfc,    // [1, H]
    const float* __restrict__ bfc,    // [1]
    float* __restrict__ out,          // [B, 1]
    int B, int T)
{
    extern __shared__ __align__(16) char smem_raw[];
    float* wsm  = (float*)smem_raw;                                   // [k][j] scalar Whh
    u64* gates  = (u64*)(smem_raw + WSM_BYTES);                       // packed by batch pair
    u64* hbuf   = (u64*)(smem_raw + WSM_BYTES + GATES_BYTES);
    u64* xs0    = (u64*)(smem_raw + WSM_BYTES + GATES_BYTES + HBUF_BYTES);
    u64* xs1    = xs0 + NP * IDIM;

    const int tid  = threadIdx.x;
    const int j    = tid & 255;       // gate row
    const int team = tid >> 8;        // 0 or 1
    const int p0   = team * TP;       // this thread's first batch pair
    const int b0   = blockIdx.x * NB;
    const int nb   = min(NB, B - b0);
    const int nx   = nb * IDIM;

    // ---- stage Whh into SMEM transposed: wsm[k*256 + j] = Whh[j][k] ----
    for (int idx = tid; idx < HDIM * GDIM; idx += NTHR) {
        const int k = idx >> 8, jj = idx & 255;
        wsm[idx] = Whh[jj * HDIM + k];
    }

    // ---- per-thread input weights + bias (16 + 2 regs) ----
    u64 wih2[IDIM];
#pragma unroll
    for (int i = 0; i < IDIM; ++i) {
        float w = Wih[j * IDIM + i];
        wih2[i] = pack2(w, w);
    }
    const float bsum = bih[j] + bhh[j];
    const u64 bias2 = pack2(bsum, bsum);

    // ---- zero h, x buffers (phantom batches stay zero -> bounded values, no OOB) ----
    for (int idx = tid; idx < NP * HDIM; idx += NTHR) hbuf[idx] = 0ull;
    for (int idx = tid; idx < NP * IDIM; idx += NTHR) { xs0[idx] = 0ull; xs1[idx] = 0ull; }

    // ---- pointwise task precompute (time-invariant): idx = tid + NTHR*r ----
    float creg[NR];
    int   goff[NR], hoff[NR];
    bool  pok[NR];
#pragma unroll
    for (int r = 0; r < NR; ++r) {
        const int idx = tid + NTHR * r;
        pok[r] = (idx < NTASK);
        const int p = idx >> 7;
        const int e = (idx >> 6) & 1;
        const int u = idx & 63;
        goff[r] = (p * GDIM + u) * 2 + e;   // float index; +128/+256/+384 for f,g,o
        hoff[r] = (p * HDIM + u) * 2 + e;
        creg[r] = 0.0f;
    }

    // ---- load x(t=0) ----
    int xp = 0, xe = 0, xi = 0;
    if (tid < nx) {
        xp = tid >> 4;
        xe = (tid >> 3) & 1;
        xi = tid & 7;
        float v = x[((size_t)(b0 + 2 * xp + xe) * T) * IDIM + xi];
        ((float*)&xs0[xp * IDIM + xi])[xe] = v;
    }
    __syncthreads();

    const float* gatesf = (const float*)gates;
    float* hbuff = (float*)hbuf;

    for (int t = 0; t < T; ++t) {
        // prefetch x(t+1)
        float xn = 0.0f;
        const bool do_x = (t + 1 < T) && (tid < nx);
        if (do_x)
            xn = x[((size_t)(b0 + 2 * xp + xe) * T + (t + 1)) * IDIM + xi];

        const u64* xcur = (t & 1) ? xs1 : xs0;

        // ---- matvec: 7 independent accumulator chains, weights chunked from SMEM ----
        u64 acc[TP];
#pragma unroll
        for (int p = 0; p < TP; ++p) {
            const u64* xv = xcur + (p0 + p) * IDIM;
            u64 a = bias2;
#pragma unroll
            for (int i = 0; i < IDIM; i += 2) {
                ulonglong2 xp2 = *(const ulonglong2*)(xv + i);
                a = ffma2(xp2.x, wih2[i], a);
                a = ffma2(xp2.y, wih2[i + 1], a);
            }
            acc[p] = a;
        }

#pragma unroll
        for (int kc = 0; kc < HDIM; kc += 8) {
            u64 wp[8];
#pragma unroll
            for (int i = 0; i < 8; ++i) {
                float w = wsm[(kc + i) * GDIM + j];   // lane-consecutive, conflict-free
                wp[i] = pack2(w, w);
            }
#pragma unroll
            for (int p = 0; p < TP; ++p) {
                const u64* hp = hbuf + (p0 + p) * HDIM + kc;
                ulonglong2 h01 = *(const ulonglong2*)(hp);
                ulonglong2 h23 = *(const ulonglong2*)(hp + 2);
                ulonglong2 h45 = *(const ulonglong2*)(hp + 4);
                ulonglong2 h67 = *(const ulonglong2*)(hp + 6);
                u64 a = acc[p];
                a = ffma2(h01.x, wp[0], a);
                a = ffma2(h01.y, wp[1], a);
                a = ffma2(h23.x, wp[2], a);
                a = ffma2(h23.y, wp[3], a);
                a = ffma2(h45.x, wp[4], a);
                a = ffma2(h45.y, wp[5], a);
                a = ffma2(h67.x, wp[6], a);
                a = ffma2(h67.y, wp[7], a);
                acc[p] = a;
            }
        }

#pragma unroll
        for (int p = 0; p < TP; ++p)
            gates[(p0 + p) * GDIM + j] = acc[p];

        // stash prefetched x (other buffer; visible after barrier)
        if (do_x) {
            u64* xnxt = ((t + 1) & 1) ? xs1 : xs0;
            ((float*)&xnxt[xp * IDIM + xi])[xe] = xn;
        }

        __syncthreads();

        // ---- pointwise: i,f,g,o -> c,h ----
#pragma unroll
        for (int r = 0; r < NR; ++r) {
            if (pok[r]) {
                const int g0 = goff[r];
                float gi = gatesf[g0];
                float gf = gatesf[g0 + 128];
                float gg = gatesf[g0 + 256];
                float go = gatesf[g0 + 384];
                float iv = sigm_f(gi);
                float fv = sigm_f(gf);
                float gv = tanh_f(gg);
                float ov = sigm_f(go);
                float c  = fmaf(fv, creg[r], iv * gv);
                creg[r] = c;
                hbuff[hoff[r]] = ov * tanh_f(c);
            }
        }
        __syncthreads();
    }

    // ---- final FC: out[b] = h_T . Wfc + bfc ----
    if (tid < nb) {
        const int p = tid >> 1, e = tid & 1;
        float sum = bfc[0];
#pragma unroll
        for (int u = 0; u < HDIM; ++u)
            sum = fmaf(hbuff[(p * HDIM + u) * 2 + e], Wfc[u], sum);
        out[b0 + tid] = sum;
    }
}

extern "C" void kernel_launch(void* const* d_in, const int* in_sizes, int n_in,
                              void* d_out, int out_size) {
    const float* x    = (const float*)d_in[0];
    const float* Wih  = (const float*)d_in[1];
    const float* Whh  = (const float*)d_in[2];
    const float* bih  = (const float*)d_in[3];
    const float* bhh  = (const float*)d_in[4];
    const float* Wfc  = (const float*)d_in[5];
    const float* bfc  = (const float*)d_in[6];
    float* out = (float*)d_out;

    const int B = out_size;                   // O = 1
    const int T = in_sizes[0] / (B * IDIM);

    cudaFuncSetAttribute(lstm_persistent_kernel,
                         cudaFuncAttributeMaxDynamicSharedMemorySize, SMEM_BYTES);

    const int grid = (B + NB - 1) / NB;
    lstm_persistent_kernel<<<grid, NTHR, SMEM_BYTES>>>(x, Wih, Whh, bih, bhh, Wfc, bfc, out, B, T);
}